// round 2
// baseline (speedup 1.0000x reference)
#include <cuda_runtime.h>
#include <math.h>
#include <float.h>
#include <stdint.h>

// ---------------------------------------------------------------------------
// ConfigurableMultiHeadAttention
//   qp = q @ Wq^T ; kp = k @ Wk^T                    (gemm_nt_kernel x2)
//   scores -> cum-thresholded softmax -> head mean    (attn_kernel, fused)
//   out = attn @ v                                    (gemm_nn_kernel)
// Shapes: B=4, Sq=Skv=1024, H=16, Dh=64, dims=1024. All fp32.
// d_out layout: [out (4*1024*1024)] [attn (4*1024*1024)]
// ---------------------------------------------------------------------------

__device__ float g_qp[4 * 1024 * 1024];
__device__ float g_kp[4 * 1024 * 1024];
__device__ float g_attn[4 * 1024 * 1024];

// ---------------------------------------------------------------------------
// GEMM NT: C[m,n] = sum_k A[m,k] * W[n,k];  M = gridDim.y*128, N=1024, K=1024
// 128x128 tile, BK=16, 256 threads, 8x8 per-thread micro-tile, reg prefetch.
// ---------------------------------------------------------------------------
__global__ __launch_bounds__(256, 2)
void gemm_nt_kernel(const float* __restrict__ A, const float* __restrict__ W,
                    float* __restrict__ C) {
    __shared__ float As[16][132];
    __shared__ float Ws[16][132];

    const int m0 = blockIdx.y * 128;
    const int n0 = blockIdx.x * 128;
    const int t  = threadIdx.x;
    const int tx = t & 15, ty = t >> 4;

    const int lrow = t >> 1;         // 0..127
    const int lk   = (t & 1) * 8;    // 0 or 8

    const float* aPtr = A + (size_t)(m0 + lrow) * 1024 + lk;
    const float* wPtr = W + (size_t)(n0 + lrow) * 1024 + lk;

    float4 a0 = *(const float4*)(aPtr);
    float4 a1 = *(const float4*)(aPtr + 4);
    float4 w0 = *(const float4*)(wPtr);
    float4 w1 = *(const float4*)(wPtr + 4);

    float acc[8][8];
#pragma unroll
    for (int i = 0; i < 8; ++i)
#pragma unroll
        for (int j = 0; j < 8; ++j) acc[i][j] = 0.f;

    for (int kb = 0; kb < 64; ++kb) {
        As[lk + 0][lrow] = a0.x; As[lk + 1][lrow] = a0.y;
        As[lk + 2][lrow] = a0.z; As[lk + 3][lrow] = a0.w;
        As[lk + 4][lrow] = a1.x; As[lk + 5][lrow] = a1.y;
        As[lk + 6][lrow] = a1.z; As[lk + 7][lrow] = a1.w;
        Ws[lk + 0][lrow] = w0.x; Ws[lk + 1][lrow] = w0.y;
        Ws[lk + 2][lrow] = w0.z; Ws[lk + 3][lrow] = w0.w;
        Ws[lk + 4][lrow] = w1.x; Ws[lk + 5][lrow] = w1.y;
        Ws[lk + 6][lrow] = w1.z; Ws[lk + 7][lrow] = w1.w;
        __syncthreads();

        if (kb < 63) {  // prefetch next k-slab into registers
            const float* ap = aPtr + (kb + 1) * 16;
            const float* wp = wPtr + (kb + 1) * 16;
            a0 = *(const float4*)(ap);     a1 = *(const float4*)(ap + 4);
            w0 = *(const float4*)(wp);     w1 = *(const float4*)(wp + 4);
        }

#pragma unroll
        for (int kk = 0; kk < 16; ++kk) {
            float4 x0 = *(const float4*)&As[kk][ty * 8];
            float4 x1 = *(const float4*)&As[kk][ty * 8 + 4];
            float4 y0 = *(const float4*)&Ws[kk][tx * 8];
            float4 y1 = *(const float4*)&Ws[kk][tx * 8 + 4];
            float av[8] = {x0.x, x0.y, x0.z, x0.w, x1.x, x1.y, x1.z, x1.w};
            float bv[8] = {y0.x, y0.y, y0.z, y0.w, y1.x, y1.y, y1.z, y1.w};
#pragma unroll
            for (int i = 0; i < 8; ++i)
#pragma unroll
                for (int j = 0; j < 8; ++j) acc[i][j] += av[i] * bv[j];
        }
        __syncthreads();
    }

#pragma unroll
    for (int i = 0; i < 8; ++i) {
        float* cp = C + (size_t)(m0 + ty * 8 + i) * 1024 + n0 + tx * 8;
        *(float4*)(cp)     = make_float4(acc[i][0], acc[i][1], acc[i][2], acc[i][3]);
        *(float4*)(cp + 4) = make_float4(acc[i][4], acc[i][5], acc[i][6], acc[i][7]);
    }
}

// ---------------------------------------------------------------------------
// GEMM NN (batched over z): C[m,n] = sum_k A[m,k] * B[k,n]; M=N=K=1024.
// ---------------------------------------------------------------------------
__global__ __launch_bounds__(256, 2)
void gemm_nn_kernel(const float* __restrict__ Ab, const float* __restrict__ Bb,
                    float* __restrict__ Cb) {
    __shared__ float As[16][132];
    __shared__ float Bs[16][132];

    const size_t boff = (size_t)blockIdx.z * 1024 * 1024;
    const float* A = Ab + boff;
    const float* B = Bb + boff;
    float*       C = Cb + boff;

    const int m0 = blockIdx.y * 128;
    const int n0 = blockIdx.x * 128;
    const int t  = threadIdx.x;
    const int tx = t & 15, ty = t >> 4;

    const int lrow = t >> 1;
    const int lk   = (t & 1) * 8;
    const float* aPtr = A + (size_t)(m0 + lrow) * 1024 + lk;

    const int bk = t >> 4;          // 0..15
    const int bn = (t & 15) * 8;    // 0..120
    const float* bPtr = B + (size_t)bk * 1024 + n0 + bn;

    float4 a0 = *(const float4*)(aPtr);
    float4 a1 = *(const float4*)(aPtr + 4);
    float4 b0 = *(const float4*)(bPtr);
    float4 b1 = *(const float4*)(bPtr + 4);

    float acc[8][8];
#pragma unroll
    for (int i = 0; i < 8; ++i)
#pragma unroll
        for (int j = 0; j < 8; ++j) acc[i][j] = 0.f;

    for (int kb = 0; kb < 64; ++kb) {
        As[lk + 0][lrow] = a0.x; As[lk + 1][lrow] = a0.y;
        As[lk + 2][lrow] = a0.z; As[lk + 3][lrow] = a0.w;
        As[lk + 4][lrow] = a1.x; As[lk + 5][lrow] = a1.y;
        As[lk + 6][lrow] = a1.z; As[lk + 7][lrow] = a1.w;
        *(float4*)&Bs[bk][bn]     = b0;
        *(float4*)&Bs[bk][bn + 4] = b1;
        __syncthreads();

        if (kb < 63) {
            const float* ap = aPtr + (kb + 1) * 16;
            const float* bp = bPtr + (size_t)(kb + 1) * 16 * 1024;
            a0 = *(const float4*)(ap); a1 = *(const float4*)(ap + 4);
            b0 = *(const float4*)(bp); b1 = *(const float4*)(bp + 4);
        }

#pragma unroll
        for (int kk = 0; kk < 16; ++kk) {
            float4 x0 = *(const float4*)&As[kk][ty * 8];
            float4 x1 = *(const float4*)&As[kk][ty * 8 + 4];
            float4 y0 = *(const float4*)&Bs[kk][tx * 8];
            float4 y1 = *(const float4*)&Bs[kk][tx * 8 + 4];
            float av[8] = {x0.x, x0.y, x0.z, x0.w, x1.x, x1.y, x1.z, x1.w};
            float bv[8] = {y0.x, y0.y, y0.z, y0.w, y1.x, y1.y, y1.z, y1.w};
#pragma unroll
            for (int i = 0; i < 8; ++i)
#pragma unroll
                for (int j = 0; j < 8; ++j) acc[i][j] += av[i] * bv[j];
        }
        __syncthreads();
    }

#pragma unroll
    for (int i = 0; i < 8; ++i) {
        float* cp = C + (size_t)(m0 + ty * 8 + i) * 1024 + n0 + tx * 8;
        *(float4*)(cp)     = make_float4(acc[i][0], acc[i][1], acc[i][2], acc[i][3]);
        *(float4*)(cp + 4) = make_float4(acc[i][4], acc[i][5], acc[i][6], acc[i][7]);
    }
}

// ---------------------------------------------------------------------------
// Fused attention: scores (per head) -> cum-thresholded softmax (exact
// weighted radix-select over positive-float bit patterns) -> mean over heads.
// CTA = (batch b, 16 q-rows). 512 threads (16 warps).
// Compute phase: warp = (rowgroup of 4, j-subtile of 32); kp tile 128x64 in
// shared with 16B-unit XOR swizzle (conflict-free LDS.128).
// Select phase: warp w owns row w; everything register-resident, warp-local.
// ---------------------------------------------------------------------------
#define ATTN_SMEM_BYTES (4096 + 32768 + 65536 + 1024)

__global__ __launch_bounds__(512)
void attn_kernel(const float* __restrict__ qp, const float* __restrict__ kp,
                 const int* __restrict__ kmask, float* __restrict__ attn,
                 float* __restrict__ attn_out) {
    extern __shared__ char smem_raw[];
    float*         qs  = (float*)smem_raw;                           // 16 x 64
    float4*        ks4 = (float4*)(smem_raw + 4096);                 // 128 x 16 float4
    float*         sc  = (float*)(smem_raw + 4096 + 32768);          // 16 x 1024
    unsigned char* km  = (unsigned char*)(smem_raw + 4096 + 32768 + 65536); // 1024

    const int b    = blockIdx.y;
    const int r0   = blockIdx.x * 16;
    const int tid  = threadIdx.x;
    const int warp = tid >> 5;
    const int lane = tid & 31;

    for (int i = tid; i < 1024; i += 512)
        km[i] = (kmask[b * 1024 + i] > 0) ? 1 : 0;

    float acc[32];
#pragma unroll
    for (int t2 = 0; t2 < 32; ++t2) acc[t2] = 0.f;

    const int rg   = (warp >> 2) * 4;            // row-group base (0,4,8,12)
    const int jloc = ((warp & 3) << 5) + lane;   // 0..127 within j-tile
    const int sw   = jloc & 15;

    for (int h = 0; h < 16; ++h) {
        {   // load q slices for this head: 16 rows x 64 d
            int row = tid >> 5;
            int d0  = (tid & 31) * 2;
            float2 qv = *(const float2*)(qp + (size_t)((b << 10) + r0 + row) * 1024
                                            + h * 64 + d0);
            qs[row * 64 + d0]     = qv.x;
            qs[row * 64 + d0 + 1] = qv.y;
        }
        __syncthreads();

        for (int jt = 0; jt < 8; ++jt) {
            {   // stage kp tile: 128 j x 64 d, XOR-swizzled in 16B units
                int j = tid >> 2;
                const float4* src = (const float4*)(kp + (size_t)((b << 10) + jt * 128 + j) * 1024
                                                       + h * 64);
                int jsw = j & 15;
#pragma unroll
                for (int e = 0; e < 4; ++e) {
                    int d4 = (tid & 3) * 4 + e;
                    ks4[j * 16 + (d4 ^ jsw)] = src[d4];
                }
            }
            __syncthreads();
            {   // each warp: 4 rows x 32 j dot-products over d=64
                const float4* kb4 = ks4 + jloc * 16;
                float a4[4] = {0.f, 0.f, 0.f, 0.f};
#pragma unroll
                for (int d8 = 0; d8 < 8; ++d8) {
                    float4 k0 = kb4[(2 * d8) ^ sw];
                    float4 k1 = kb4[(2 * d8 + 1) ^ sw];
#pragma unroll
                    for (int rr = 0; rr < 4; ++rr) {
                        const float* qrow = qs + (rg + rr) * 64 + d8 * 8;
                        float4 qa = *(const float4*)(qrow);
                        float4 qb = *(const float4*)(qrow + 4);
                        a4[rr] += qa.x * k0.x + qa.y * k0.y + qa.z * k0.z + qa.w * k0.w
                                + qb.x * k1.x + qb.y * k1.y + qb.z * k1.z + qb.w * k1.w;
                    }
                }
                int j = jt * 128 + jloc;
#pragma unroll
                for (int rr = 0; rr < 4; ++rr)
                    sc[(rg + rr) * 1024 + j] = a4[rr] * 0.125f;  // scale = 1/sqrt(64)
            }
            __syncthreads();
        }

        // ---- per-row softmax + cumulative threshold select (warp w = row w)
        {
            float p[32];
            float m = -FLT_MAX;
#pragma unroll
            for (int t2 = 0; t2 < 32; ++t2) {
                int j = t2 * 32 + lane;
                float v = sc[warp * 1024 + j];
                v = km[j] ? v : -FLT_MAX;
                p[t2] = v;
                m = fmaxf(m, v);
            }
#pragma unroll
            for (int o = 16; o > 0; o >>= 1)
                m = fmaxf(m, __shfl_xor_sync(0xffffffffu, m, o));

            float Z = 0.f;
#pragma unroll
            for (int t2 = 0; t2 < 32; ++t2) {
                float e = __expf(p[t2] - m);
                p[t2] = e;
                Z += e;
            }
#pragma unroll
            for (int o = 16; o > 0; o >>= 1)
                Z += __shfl_xor_sync(0xffffffffu, Z, o);

            const float T = 0.1f * Z;

            // weighted radix-select: find P = bit pattern of the first sorted
            // element whose inclusive cumulative sum reaches T.
            // Invariant: G(P) = sum_{bits(p) < P} p < T.
            unsigned P = 0;
            for (int bit = 29; bit >= 0; --bit) {
                unsigned cand = P + (1u << bit);
                float S = 0.f;
#pragma unroll
                for (int t2 = 0; t2 < 32; ++t2)
                    S += (__float_as_uint(p[t2]) < cand) ? p[t2] : 0.f;
#pragma unroll
                for (int o = 16; o > 0; o >>= 1)
                    S += __shfl_xor_sync(0xffffffffu, S, o);
                if (S < T) P = cand;
            }

            float K = 0.f;
#pragma unroll
            for (int t2 = 0; t2 < 32; ++t2)
                K += (__float_as_uint(p[t2]) >= P) ? p[t2] : 0.f;
#pragma unroll
            for (int o = 16; o > 0; o >>= 1)
                K += __shfl_xor_sync(0xffffffffu, K, o);

            // norm_i = p_i / (K + 1e-7 * Z)   (== act/(sum(act)+eps) in s-space)
            float inv = 1.f / (K + 1e-7f * Z);
#pragma unroll
            for (int t2 = 0; t2 < 32; ++t2)
                acc[t2] += (__float_as_uint(p[t2]) >= P) ? p[t2] * inv : 0.f;
        }
        __syncthreads();
    }

    {   // write head-mean attention row
        size_t base = ((size_t)((b << 10) + r0 + warp)) << 10;
#pragma unroll
        for (int t2 = 0; t2 < 32; ++t2) {
            float vv = acc[t2] * 0.0625f;  // /16 heads
            int j = t2 * 32 + lane;
            attn[base + j] = vv;
            if (attn_out) attn_out[base + j] = vv;
        }
    }
}

// ---------------------------------------------------------------------------
// Launch
// ---------------------------------------------------------------------------
extern "C" void kernel_launch(void* const* d_in, const int* in_sizes, int n_in,
                              void* d_out, int out_size) {
    const float* q     = (const float*)d_in[0];
    const float* k     = (const float*)d_in[1];
    const float* v     = (const float*)d_in[2];
    const float* Wq    = (const float*)d_in[3];
    const float* Wk    = (const float*)d_in[4];
    const int*   kmask = (const int*)d_in[5];
    float*       out   = (float*)d_out;

    float *qp_ptr, *kp_ptr, *attn_ptr;
    cudaGetSymbolAddress((void**)&qp_ptr, g_qp);
    cudaGetSymbolAddress((void**)&kp_ptr, g_kp);
    cudaGetSymbolAddress((void**)&attn_ptr, g_attn);

    float* attn_out = (out_size >= 2 * 4194304) ? (out + 4194304) : nullptr;

    // projections: qp = q@Wq^T, kp = k@Wk^T (M=4096, N=K=1024)
    dim3 gproj(8, 32);
    gemm_nt_kernel<<<gproj, 256>>>(q, Wq, qp_ptr);
    gemm_nt_kernel<<<gproj, 256>>>(k, Wk, kp_ptr);

    // fused scores + thresholded softmax + head mean
    cudaFuncSetAttribute(attn_kernel, cudaFuncAttributeMaxDynamicSharedMemorySize,
                         ATTN_SMEM_BYTES);
    attn_kernel<<<dim3(64, 4), 512, ATTN_SMEM_BYTES>>>(qp_ptr, kp_ptr, kmask,
                                                       attn_ptr, attn_out);

    // out = attn @ v (batched 1024^3)
    gemm_nn_kernel<<<dim3(8, 8, 4), 256>>>(attn_ptr, v, out);
}

// round 3
// speedup vs baseline: 1.0043x; 1.0043x over previous
#include <cuda_runtime.h>
#include <math.h>
#include <float.h>
#include <stdint.h>

// ---------------------------------------------------------------------------
// ConfigurableMultiHeadAttention
//   qp = q @ Wq^T ; kp = k @ Wk^T                    (gemm_nt_kernel x2)
//   scores -> cum-thresholded softmax -> head mean    (attn_kernel, fused)
//   out = attn @ v                                    (gemm_nn_kernel)
// Shapes: B=4, Sq=Skv=1024, H=16, Dh=64, dims=1024. All fp32.
// d_out layout: [out (4*1024*1024)] [attn (4*1024*1024)]
// ---------------------------------------------------------------------------

__device__ float g_qp[4 * 1024 * 1024];
__device__ float g_kp[4 * 1024 * 1024];
__device__ float g_attn[4 * 1024 * 1024];

// ---------------------------------------------------------------------------
// GEMM NT: C[m,n] = sum_k A[m,k] * W[n,k];  M = gridDim.y*128, N=1024, K=1024
// 128x128 tile, BK=16, 256 threads, 8x8 per-thread micro-tile, reg prefetch.
// ---------------------------------------------------------------------------
__global__ __launch_bounds__(256, 2)
void gemm_nt_kernel(const float* __restrict__ A, const float* __restrict__ W,
                    float* __restrict__ C) {
    __shared__ float As[16][132];
    __shared__ float Ws[16][132];

    const int m0 = blockIdx.y * 128;
    const int n0 = blockIdx.x * 128;
    const int t  = threadIdx.x;
    const int tx = t & 15, ty = t >> 4;

    const int lrow = t >> 1;         // 0..127
    const int lk   = (t & 1) * 8;    // 0 or 8

    const float* aPtr = A + (size_t)(m0 + lrow) * 1024 + lk;
    const float* wPtr = W + (size_t)(n0 + lrow) * 1024 + lk;

    float4 a0 = *(const float4*)(aPtr);
    float4 a1 = *(const float4*)(aPtr + 4);
    float4 w0 = *(const float4*)(wPtr);
    float4 w1 = *(const float4*)(wPtr + 4);

    float acc[8][8];
#pragma unroll
    for (int i = 0; i < 8; ++i)
#pragma unroll
        for (int j = 0; j < 8; ++j) acc[i][j] = 0.f;

    for (int kb = 0; kb < 64; ++kb) {
        As[lk + 0][lrow] = a0.x; As[lk + 1][lrow] = a0.y;
        As[lk + 2][lrow] = a0.z; As[lk + 3][lrow] = a0.w;
        As[lk + 4][lrow] = a1.x; As[lk + 5][lrow] = a1.y;
        As[lk + 6][lrow] = a1.z; As[lk + 7][lrow] = a1.w;
        Ws[lk + 0][lrow] = w0.x; Ws[lk + 1][lrow] = w0.y;
        Ws[lk + 2][lrow] = w0.z; Ws[lk + 3][lrow] = w0.w;
        Ws[lk + 4][lrow] = w1.x; Ws[lk + 5][lrow] = w1.y;
        Ws[lk + 6][lrow] = w1.z; Ws[lk + 7][lrow] = w1.w;
        __syncthreads();

        if (kb < 63) {  // prefetch next k-slab into registers
            const float* ap = aPtr + (kb + 1) * 16;
            const float* wp = wPtr + (kb + 1) * 16;
            a0 = *(const float4*)(ap);     a1 = *(const float4*)(ap + 4);
            w0 = *(const float4*)(wp);     w1 = *(const float4*)(wp + 4);
        }

#pragma unroll
        for (int kk = 0; kk < 16; ++kk) {
            float4 x0 = *(const float4*)&As[kk][ty * 8];
            float4 x1 = *(const float4*)&As[kk][ty * 8 + 4];
            float4 y0 = *(const float4*)&Ws[kk][tx * 8];
            float4 y1 = *(const float4*)&Ws[kk][tx * 8 + 4];
            float av[8] = {x0.x, x0.y, x0.z, x0.w, x1.x, x1.y, x1.z, x1.w};
            float bv[8] = {y0.x, y0.y, y0.z, y0.w, y1.x, y1.y, y1.z, y1.w};
#pragma unroll
            for (int i = 0; i < 8; ++i)
#pragma unroll
                for (int j = 0; j < 8; ++j) acc[i][j] += av[i] * bv[j];
        }
        __syncthreads();
    }

#pragma unroll
    for (int i = 0; i < 8; ++i) {
        float* cp = C + (size_t)(m0 + ty * 8 + i) * 1024 + n0 + tx * 8;
        *(float4*)(cp)     = make_float4(acc[i][0], acc[i][1], acc[i][2], acc[i][3]);
        *(float4*)(cp + 4) = make_float4(acc[i][4], acc[i][5], acc[i][6], acc[i][7]);
    }
}

// ---------------------------------------------------------------------------
// GEMM NN (batched over z): C[m,n] = sum_k A[m,k] * B[k,n]; M=N=K=1024.
// ---------------------------------------------------------------------------
__global__ __launch_bounds__(256, 2)
void gemm_nn_kernel(const float* __restrict__ Ab, const float* __restrict__ Bb,
                    float* __restrict__ Cb) {
    __shared__ float As[16][132];
    __shared__ float Bs[16][132];

    const size_t boff = (size_t)blockIdx.z * 1024 * 1024;
    const float* A = Ab + boff;
    const float* B = Bb + boff;
    float*       C = Cb + boff;

    const int m0 = blockIdx.y * 128;
    const int n0 = blockIdx.x * 128;
    const int t  = threadIdx.x;
    const int tx = t & 15, ty = t >> 4;

    const int lrow = t >> 1;
    const int lk   = (t & 1) * 8;
    const float* aPtr = A + (size_t)(m0 + lrow) * 1024 + lk;

    const int bk = t >> 4;          // 0..15
    const int bn = (t & 15) * 8;    // 0..120
    const float* bPtr = B + (size_t)bk * 1024 + n0 + bn;

    float4 a0 = *(const float4*)(aPtr);
    float4 a1 = *(const float4*)(aPtr + 4);
    float4 b0 = *(const float4*)(bPtr);
    float4 b1 = *(const float4*)(bPtr + 4);

    float acc[8][8];
#pragma unroll
    for (int i = 0; i < 8; ++i)
#pragma unroll
        for (int j = 0; j < 8; ++j) acc[i][j] = 0.f;

    for (int kb = 0; kb < 64; ++kb) {
        As[lk + 0][lrow] = a0.x; As[lk + 1][lrow] = a0.y;
        As[lk + 2][lrow] = a0.z; As[lk + 3][lrow] = a0.w;
        As[lk + 4][lrow] = a1.x; As[lk + 5][lrow] = a1.y;
        As[lk + 6][lrow] = a1.z; As[lk + 7][lrow] = a1.w;
        *(float4*)&Bs[bk][bn]     = b0;
        *(float4*)&Bs[bk][bn + 4] = b1;
        __syncthreads();

        if (kb < 63) {
            const float* ap = aPtr + (kb + 1) * 16;
            const float* bp = bPtr + (size_t)(kb + 1) * 16 * 1024;
            a0 = *(const float4*)(ap); a1 = *(const float4*)(ap + 4);
            b0 = *(const float4*)(bp); b1 = *(const float4*)(bp + 4);
        }

#pragma unroll
        for (int kk = 0; kk < 16; ++kk) {
            float4 x0 = *(const float4*)&As[kk][ty * 8];
            float4 x1 = *(const float4*)&As[kk][ty * 8 + 4];
            float4 y0 = *(const float4*)&Bs[kk][tx * 8];
            float4 y1 = *(const float4*)&Bs[kk][tx * 8 + 4];
            float av[8] = {x0.x, x0.y, x0.z, x0.w, x1.x, x1.y, x1.z, x1.w};
            float bv[8] = {y0.x, y0.y, y0.z, y0.w, y1.x, y1.y, y1.z, y1.w};
#pragma unroll
            for (int i = 0; i < 8; ++i)
#pragma unroll
                for (int j = 0; j < 8; ++j) acc[i][j] += av[i] * bv[j];
        }
        __syncthreads();
    }

#pragma unroll
    for (int i = 0; i < 8; ++i) {
        float* cp = C + (size_t)(m0 + ty * 8 + i) * 1024 + n0 + tx * 8;
        *(float4*)(cp)     = make_float4(acc[i][0], acc[i][1], acc[i][2], acc[i][3]);
        *(float4*)(cp + 4) = make_float4(acc[i][4], acc[i][5], acc[i][6], acc[i][7]);
    }
}

// ---------------------------------------------------------------------------
// Fused attention: scores (per head) -> cum-thresholded softmax (exact
// weighted radix-select over positive-float bit patterns) -> mean over heads.
// CTA = (batch b, 16 q-rows). 512 threads (16 warps).
// Compute phase: warp = (rowgroup of 4, j-subtile of 32); kp tile 128x64 in
// shared with 16B-unit XOR swizzle (conflict-free LDS.128).
// Select phase: warp w owns row w; everything register-resident, warp-local.
// ---------------------------------------------------------------------------
#define ATTN_SMEM_BYTES (4096 + 32768 + 65536 + 1024)

__global__ __launch_bounds__(512)
void attn_kernel(const float* __restrict__ qp, const float* __restrict__ kp,
                 const int* __restrict__ kmask, float* __restrict__ attn,
                 float* __restrict__ attn_out) {
    extern __shared__ char smem_raw[];
    float*         qs  = (float*)smem_raw;                           // 16 x 64
    float4*        ks4 = (float4*)(smem_raw + 4096);                 // 128 x 16 float4
    float*         sc  = (float*)(smem_raw + 4096 + 32768);          // 16 x 1024
    unsigned char* km  = (unsigned char*)(smem_raw + 4096 + 32768 + 65536); // 1024

    const int b    = blockIdx.y;
    const int r0   = blockIdx.x * 16;
    const int tid  = threadIdx.x;
    const int warp = tid >> 5;
    const int lane = tid & 31;

    for (int i = tid; i < 1024; i += 512)
        km[i] = (kmask[b * 1024 + i] > 0) ? 1 : 0;

    float acc[32];
#pragma unroll
    for (int t2 = 0; t2 < 32; ++t2) acc[t2] = 0.f;

    const int rg   = (warp >> 2) * 4;            // row-group base (0,4,8,12)
    const int jloc = ((warp & 3) << 5) + lane;   // 0..127 within j-tile
    const int sw   = jloc & 15;

    for (int h = 0; h < 16; ++h) {
        {   // load q slices for this head: 16 rows x 64 d
            int row = tid >> 5;
            int d0  = (tid & 31) * 2;
            float2 qv = *(const float2*)(qp + (size_t)((b << 10) + r0 + row) * 1024
                                            + h * 64 + d0);
            qs[row * 64 + d0]     = qv.x;
            qs[row * 64 + d0 + 1] = qv.y;
        }
        __syncthreads();

        for (int jt = 0; jt < 8; ++jt) {
            {   // stage kp tile: 128 j x 64 d, XOR-swizzled in 16B units
                int j = tid >> 2;
                const float4* src = (const float4*)(kp + (size_t)((b << 10) + jt * 128 + j) * 1024
                                                       + h * 64);
                int jsw = j & 15;
#pragma unroll
                for (int e = 0; e < 4; ++e) {
                    int d4 = (tid & 3) * 4 + e;
                    ks4[j * 16 + (d4 ^ jsw)] = src[d4];
                }
            }
            __syncthreads();
            {   // each warp: 4 rows x 32 j dot-products over d=64
                const float4* kb4 = ks4 + jloc * 16;
                float a4[4] = {0.f, 0.f, 0.f, 0.f};
#pragma unroll
                for (int d8 = 0; d8 < 8; ++d8) {
                    float4 k0 = kb4[(2 * d8) ^ sw];
                    float4 k1 = kb4[(2 * d8 + 1) ^ sw];
#pragma unroll
                    for (int rr = 0; rr < 4; ++rr) {
                        const float* qrow = qs + (rg + rr) * 64 + d8 * 8;
                        float4 qa = *(const float4*)(qrow);
                        float4 qb = *(const float4*)(qrow + 4);
                        a4[rr] += qa.x * k0.x + qa.y * k0.y + qa.z * k0.z + qa.w * k0.w
                                + qb.x * k1.x + qb.y * k1.y + qb.z * k1.z + qb.w * k1.w;
                    }
                }
                int j = jt * 128 + jloc;
#pragma unroll
                for (int rr = 0; rr < 4; ++rr)
                    sc[(rg + rr) * 1024 + j] = a4[rr] * 0.125f;  // scale = 1/sqrt(64)
            }
            __syncthreads();
        }

        // ---- per-row softmax + cumulative threshold select (warp w = row w)
        {
            float p[32];
            float m = -FLT_MAX;
#pragma unroll
            for (int t2 = 0; t2 < 32; ++t2) {
                int j = t2 * 32 + lane;
                float v = sc[warp * 1024 + j];
                v = km[j] ? v : -FLT_MAX;
                p[t2] = v;
                m = fmaxf(m, v);
            }
#pragma unroll
            for (int o = 16; o > 0; o >>= 1)
                m = fmaxf(m, __shfl_xor_sync(0xffffffffu, m, o));

            float Z = 0.f;
#pragma unroll
            for (int t2 = 0; t2 < 32; ++t2) {
                float e = __expf(p[t2] - m);
                p[t2] = e;
                Z += e;
            }
#pragma unroll
            for (int o = 16; o > 0; o >>= 1)
                Z += __shfl_xor_sync(0xffffffffu, Z, o);

            const float T = 0.1f * Z;

            // weighted radix-select: find P = bit pattern of the first sorted
            // element whose inclusive cumulative sum reaches T.
            // Invariant: G(P) = sum_{bits(p) < P} p < T.
            unsigned P = 0;
            for (int bit = 29; bit >= 0; --bit) {
                unsigned cand = P + (1u << bit);
                float S = 0.f;
#pragma unroll
                for (int t2 = 0; t2 < 32; ++t2)
                    S += (__float_as_uint(p[t2]) < cand) ? p[t2] : 0.f;
#pragma unroll
                for (int o = 16; o > 0; o >>= 1)
                    S += __shfl_xor_sync(0xffffffffu, S, o);
                if (S < T) P = cand;
            }

            float K = 0.f;
#pragma unroll
            for (int t2 = 0; t2 < 32; ++t2)
                K += (__float_as_uint(p[t2]) >= P) ? p[t2] : 0.f;
#pragma unroll
            for (int o = 16; o > 0; o >>= 1)
                K += __shfl_xor_sync(0xffffffffu, K, o);

            // norm_i = p_i / (K + 1e-7 * Z)   (== act/(sum(act)+eps) in s-space)
            float inv = 1.f / (K + 1e-7f * Z);
#pragma unroll
            for (int t2 = 0; t2 < 32; ++t2)
                acc[t2] += (__float_as_uint(p[t2]) >= P) ? p[t2] * inv : 0.f;
        }
        __syncthreads();
    }

    {   // write head-mean attention row
        size_t base = ((size_t)((b << 10) + r0 + warp)) << 10;
#pragma unroll
        for (int t2 = 0; t2 < 32; ++t2) {
            float vv = acc[t2] * 0.0625f;  // /16 heads
            int j = t2 * 32 + lane;
            attn[base + j] = vv;
            if (attn_out) attn_out[base + j] = vv;
        }
    }
}

// ---------------------------------------------------------------------------
// Launch
// ---------------------------------------------------------------------------
extern "C" void kernel_launch(void* const* d_in, const int* in_sizes, int n_in,
                              void* d_out, int out_size) {
    const float* q     = (const float*)d_in[0];
    const float* k     = (const float*)d_in[1];
    const float* v     = (const float*)d_in[2];
    const float* Wq    = (const float*)d_in[3];
    const float* Wk    = (const float*)d_in[4];
    const int*   kmask = (const int*)d_in[5];
    float*       out   = (float*)d_out;

    float *qp_ptr, *kp_ptr, *attn_ptr;
    cudaGetSymbolAddress((void**)&qp_ptr, g_qp);
    cudaGetSymbolAddress((void**)&kp_ptr, g_kp);
    cudaGetSymbolAddress((void**)&attn_ptr, g_attn);

    float* attn_out = (out_size >= 2 * 4194304) ? (out + 4194304) : nullptr;

    // projections: qp = q@Wq^T, kp = k@Wk^T (M=4096, N=K=1024)
    dim3 gproj(8, 32);
    gemm_nt_kernel<<<gproj, 256>>>(q, Wq, qp_ptr);
    gemm_nt_kernel<<<gproj, 256>>>(k, Wk, kp_ptr);

    // fused scores + thresholded softmax + head mean
    cudaFuncSetAttribute(attn_kernel, cudaFuncAttributeMaxDynamicSharedMemorySize,
                         ATTN_SMEM_BYTES);
    attn_kernel<<<dim3(64, 4), 512, ATTN_SMEM_BYTES>>>(qp_ptr, kp_ptr, kmask,
                                                       attn_ptr, attn_out);

    // out = attn @ v (batched 1024^3)
    gemm_nn_kernel<<<dim3(8, 8, 4), 256>>>(attn_ptr, v, out);
}

// round 4
// speedup vs baseline: 1.2795x; 1.2740x over previous
#include <cuda_runtime.h>
#include <math.h>
#include <float.h>
#include <stdint.h>

// Shapes: B=4, Sq=Skv=1024, H=16, Dh=64, dims=1024. fp32.
// d_out: [out 4M][attn 4M]
__device__ float g_qp[4 * 1024 * 1024];
__device__ float g_kp[4 * 1024 * 1024];
__device__ float g_kT[4 * 1024 * 1024];
__device__ float g_attn[4 * 1024 * 1024];

// ---------------- GEMM NT: C = A @ W^T, M=4096,N=K=1024; z picks (q,k) ------
__global__ __launch_bounds__(256, 2)
void gemm_nt_kernel(const float* __restrict__ A0, const float* __restrict__ W0,
                    float* __restrict__ C0,
                    const float* __restrict__ A1, const float* __restrict__ W1,
                    float* __restrict__ C1) {
    __shared__ float As[16][132];
    __shared__ float Ws[16][132];
    const float* A = blockIdx.z ? A1 : A0;
    const float* W = blockIdx.z ? W1 : W0;
    float*       C = blockIdx.z ? C1 : C0;

    const int m0 = blockIdx.y * 128, n0 = blockIdx.x * 128;
    const int t = threadIdx.x, tx = t & 15, ty = t >> 4;
    const int lrow = t >> 1, lk = (t & 1) * 8;

    const float* aPtr = A + (size_t)(m0 + lrow) * 1024 + lk;
    const float* wPtr = W + (size_t)(n0 + lrow) * 1024 + lk;
    float4 a0 = *(const float4*)(aPtr),     a1 = *(const float4*)(aPtr + 4);
    float4 w0 = *(const float4*)(wPtr),     w1 = *(const float4*)(wPtr + 4);

    float acc[8][8];
#pragma unroll
    for (int i = 0; i < 8; ++i)
#pragma unroll
        for (int j = 0; j < 8; ++j) acc[i][j] = 0.f;

    for (int kb = 0; kb < 64; ++kb) {
        As[lk+0][lrow]=a0.x; As[lk+1][lrow]=a0.y; As[lk+2][lrow]=a0.z; As[lk+3][lrow]=a0.w;
        As[lk+4][lrow]=a1.x; As[lk+5][lrow]=a1.y; As[lk+6][lrow]=a1.z; As[lk+7][lrow]=a1.w;
        Ws[lk+0][lrow]=w0.x; Ws[lk+1][lrow]=w0.y; Ws[lk+2][lrow]=w0.z; Ws[lk+3][lrow]=w0.w;
        Ws[lk+4][lrow]=w1.x; Ws[lk+5][lrow]=w1.y; Ws[lk+6][lrow]=w1.z; Ws[lk+7][lrow]=w1.w;
        __syncthreads();
        if (kb < 63) {
            const float* ap = aPtr + (kb + 1) * 16;
            const float* wp = wPtr + (kb + 1) * 16;
            a0 = *(const float4*)(ap); a1 = *(const float4*)(ap + 4);
            w0 = *(const float4*)(wp); w1 = *(const float4*)(wp + 4);
        }
#pragma unroll
        for (int kk = 0; kk < 16; ++kk) {
            float4 x0 = *(const float4*)&As[kk][ty*8];
            float4 x1 = *(const float4*)&As[kk][ty*8+4];
            float4 y0 = *(const float4*)&Ws[kk][tx*8];
            float4 y1 = *(const float4*)&Ws[kk][tx*8+4];
            float av[8] = {x0.x,x0.y,x0.z,x0.w,x1.x,x1.y,x1.z,x1.w};
            float bv[8] = {y0.x,y0.y,y0.z,y0.w,y1.x,y1.y,y1.z,y1.w};
#pragma unroll
            for (int i = 0; i < 8; ++i)
#pragma unroll
                for (int j = 0; j < 8; ++j) acc[i][j] += av[i] * bv[j];
        }
        __syncthreads();
    }
#pragma unroll
    for (int i = 0; i < 8; ++i) {
        float* cp = C + (size_t)(m0 + ty*8 + i) * 1024 + n0 + tx*8;
        *(float4*)(cp)   = make_float4(acc[i][0],acc[i][1],acc[i][2],acc[i][3]);
        *(float4*)(cp+4) = make_float4(acc[i][4],acc[i][5],acc[i][6],acc[i][7]);
    }
}

// ---------------- GEMM NN batched: C = A @ B, 1024^3 per batch --------------
__global__ __launch_bounds__(256, 2)
void gemm_nn_kernel(const float* __restrict__ Ab, const float* __restrict__ Bb,
                    float* __restrict__ Cb) {
    __shared__ float As[16][132];
    __shared__ float Bs[16][132];
    const size_t boff = (size_t)blockIdx.z * 1024 * 1024;
    const float* A = Ab + boff;
    const float* B = Bb + boff;
    float*       C = Cb + boff;

    const int m0 = blockIdx.y * 128, n0 = blockIdx.x * 128;
    const int t = threadIdx.x, tx = t & 15, ty = t >> 4;
    const int lrow = t >> 1, lk = (t & 1) * 8;
    const float* aPtr = A + (size_t)(m0 + lrow) * 1024 + lk;
    const int bk = t >> 4, bn = (t & 15) * 8;
    const float* bPtr = B + (size_t)bk * 1024 + n0 + bn;

    float4 a0 = *(const float4*)(aPtr), a1 = *(const float4*)(aPtr + 4);
    float4 b0 = *(const float4*)(bPtr), b1 = *(const float4*)(bPtr + 4);

    float acc[8][8];
#pragma unroll
    for (int i = 0; i < 8; ++i)
#pragma unroll
        for (int j = 0; j < 8; ++j) acc[i][j] = 0.f;

    for (int kb = 0; kb < 64; ++kb) {
        As[lk+0][lrow]=a0.x; As[lk+1][lrow]=a0.y; As[lk+2][lrow]=a0.z; As[lk+3][lrow]=a0.w;
        As[lk+4][lrow]=a1.x; As[lk+5][lrow]=a1.y; As[lk+6][lrow]=a1.z; As[lk+7][lrow]=a1.w;
        *(float4*)&Bs[bk][bn]   = b0;
        *(float4*)&Bs[bk][bn+4] = b1;
        __syncthreads();
        if (kb < 63) {
            const float* ap = aPtr + (kb + 1) * 16;
            const float* bp = bPtr + (size_t)(kb + 1) * 16 * 1024;
            a0 = *(const float4*)(ap); a1 = *(const float4*)(ap + 4);
            b0 = *(const float4*)(bp); b1 = *(const float4*)(bp + 4);
        }
#pragma unroll
        for (int kk = 0; kk < 16; ++kk) {
            float4 x0 = *(const float4*)&As[kk][ty*8];
            float4 x1 = *(const float4*)&As[kk][ty*8+4];
            float4 y0 = *(const float4*)&Bs[kk][tx*8];
            float4 y1 = *(const float4*)&Bs[kk][tx*8+4];
            float av[8] = {x0.x,x0.y,x0.z,x0.w,x1.x,x1.y,x1.z,x1.w};
            float bv[8] = {y0.x,y0.y,y0.z,y0.w,y1.x,y1.y,y1.z,y1.w};
#pragma unroll
            for (int i = 0; i < 8; ++i)
#pragma unroll
                for (int j = 0; j < 8; ++j) acc[i][j] += av[i] * bv[j];
        }
        __syncthreads();
    }
#pragma unroll
    for (int i = 0; i < 8; ++i) {
        float* cp = C + (size_t)(m0 + ty*8 + i) * 1024 + n0 + tx*8;
        *(float4*)(cp)   = make_float4(acc[i][0],acc[i][1],acc[i][2],acc[i][3]);
        *(float4*)(cp+4) = make_float4(acc[i][4],acc[i][5],acc[i][6],acc[i][7]);
    }
}

// ---------------- Transpose: kp[b][j][d] -> kT[b][d][j] ---------------------
__global__ __launch_bounds__(256)
void transpose_kernel(const float* __restrict__ in, float* __restrict__ out) {
    __shared__ float tile[32][33];
    const int b = blockIdx.z;
    const int d0 = blockIdx.x * 32, j0 = blockIdx.y * 32;
    const int tx = threadIdx.x & 31, ty = threadIdx.x >> 5;   // ty 0..7
    const float* I = in  + ((size_t)b << 20);
    float*       O = out + ((size_t)b << 20);
#pragma unroll
    for (int i = 0; i < 4; ++i)
        tile[ty + i*8][tx] = I[(size_t)(j0 + ty + i*8) * 1024 + d0 + tx];
    __syncthreads();
#pragma unroll
    for (int i = 0; i < 4; ++i)
        O[(size_t)(d0 + ty + i*8) * 1024 + j0 + tx] = tile[tx][ty + i*8];
}

// ---------------- Fused attention ------------------------------------------
// CTA = (batch b, 8 q-rows), 256 thr / 8 warps, 2 CTAs/SM.
// Compute: warp w owns j in [w*128, w*128+128), lane owns 4 consecutive j.
//   k staged along j (from kT) -> lane-distinct LDS.128; q -> broadcast LDS.
// Select: warp w owns row w; exact weighted radix-select, 27 rounds.
__global__ __launch_bounds__(256, 2)
void attn_kernel(const float* __restrict__ qp, const float* __restrict__ kT,
                 const int* __restrict__ kmask, float* __restrict__ attn,
                 float* __restrict__ attn_out) {
    __shared__ float ks[8][1024];          // 32 KB; reused as sc[8][1024]
    __shared__ float qs[8][64];
    __shared__ unsigned char km[1024];

    const int b = blockIdx.y, r0 = blockIdx.x * 8;
    const int tid = threadIdx.x, warp = tid >> 5, lane = tid & 31;
    const int jb = warp * 128 + lane * 4;  // lane's 4-column base
    float* sc = &ks[0][0];

    for (int i = tid; i < 1024; i += 256)
        km[i] = (kmask[b * 1024 + i] > 0) ? 1 : 0;

    float acc[32];
#pragma unroll
    for (int t2 = 0; t2 < 32; ++t2) acc[t2] = 0.f;

    for (int h = 0; h < 16; ++h) {
        if (tid < 128) {  // stage q: 8 rows x 64 d, pre-scaled by 1/sqrt(64)
            int r = tid >> 4, d4 = (tid & 15) * 4;
            float4 v = *(const float4*)(qp + (size_t)((b << 10) + r0 + r) * 1024 + h * 64 + d4);
            v.x *= 0.125f; v.y *= 0.125f; v.z *= 0.125f; v.w *= 0.125f;
            *(float4*)&qs[r][d4] = v;
        }
        float S[32];
#pragma unroll
        for (int i = 0; i < 32; ++i) S[i] = 0.f;

        for (int dc = 0; dc < 64; dc += 8) {
            // stage ks[8][1024]: warp w loads d-row (h*64+dc+w)
            const float* src = kT + ((size_t)((b << 10) + (h << 6) + dc + warp) << 10);
#pragma unroll
            for (int i = 0; i < 8; ++i)
                *(float4*)&ks[warp][lane*4 + i*128] = *(const float4*)(src + lane*4 + i*128);
            __syncthreads();
#pragma unroll
            for (int dq = 0; dq < 8; dq += 4) {
                float4 k0 = *(const float4*)&ks[dq+0][jb];
                float4 k1 = *(const float4*)&ks[dq+1][jb];
                float4 k2 = *(const float4*)&ks[dq+2][jb];
                float4 k3 = *(const float4*)&ks[dq+3][jb];
#pragma unroll
                for (int r = 0; r < 8; ++r) {
                    float4 qv = *(const float4*)&qs[r][dc + dq];
                    S[r*4+0] += qv.x*k0.x + qv.y*k1.x + qv.z*k2.x + qv.w*k3.x;
                    S[r*4+1] += qv.x*k0.y + qv.y*k1.y + qv.z*k2.y + qv.w*k3.y;
                    S[r*4+2] += qv.x*k0.z + qv.y*k1.z + qv.z*k2.z + qv.w*k3.z;
                    S[r*4+3] += qv.x*k0.w + qv.y*k1.w + qv.z*k2.w + qv.w*k3.w;
                }
            }
            __syncthreads();  // all reads of ks done before restage/reuse
        }

        // scatter scores to sc[r][j] (reusing ks memory)
#pragma unroll
        for (int r = 0; r < 8; ++r)
            *(float4*)&sc[r*1024 + jb] = make_float4(S[r*4+0], S[r*4+1], S[r*4+2], S[r*4+3]);
        __syncthreads();

        // ---- per-row softmax + exact cumulative-threshold select (row=warp)
        {
            float p[32];
            float m = -FLT_MAX;
#pragma unroll
            for (int t2 = 0; t2 < 32; ++t2) {
                int j = t2 * 32 + lane;
                float v = sc[warp * 1024 + j];
                v = km[j] ? v : -FLT_MAX;
                p[t2] = v;
                m = fmaxf(m, v);
            }
#pragma unroll
            for (int o = 16; o > 0; o >>= 1)
                m = fmaxf(m, __shfl_xor_sync(0xffffffffu, m, o));

            float Z = 0.f;
#pragma unroll
            for (int t2 = 0; t2 < 32; ++t2) {
                float e = __expf(p[t2] - m);
                p[t2] = e;
                Z += e;
            }
#pragma unroll
            for (int o = 16; o > 0; o >>= 1)
                Z += __shfl_xor_sync(0xffffffffu, Z, o);

            const float T = 0.1f * Z;
            // exact weighted radix-select. Base 0x38000000 is provably below
            // the cutoff: max p = 1.0, so G(2^-14) <= 1023*2^-14 < 0.1 <= T.
            unsigned P = 0x38000000u;
            for (int bit = 26; bit >= 0; --bit) {
                unsigned cand = P + (1u << bit);
                float Ssum = 0.f;
#pragma unroll
                for (int t2 = 0; t2 < 32; ++t2)
                    Ssum += (__float_as_uint(p[t2]) < cand) ? p[t2] : 0.f;
#pragma unroll
                for (int o = 16; o > 0; o >>= 1)
                    Ssum += __shfl_xor_sync(0xffffffffu, Ssum, o);
                if (Ssum < T) P = cand;
            }

            float K = 0.f;
#pragma unroll
            for (int t2 = 0; t2 < 32; ++t2)
                K += (__float_as_uint(p[t2]) >= P) ? p[t2] : 0.f;
#pragma unroll
            for (int o = 16; o > 0; o >>= 1)
                K += __shfl_xor_sync(0xffffffffu, K, o);

            float inv = 1.f / (K + 1e-7f * Z);
#pragma unroll
            for (int t2 = 0; t2 < 32; ++t2)
                acc[t2] += (__float_as_uint(p[t2]) >= P) ? p[t2] * inv : 0.f;
        }
        __syncthreads();  // sc reads done before next head's ks staging
    }

    {   // head-mean attention row (row = warp)
        size_t base = ((size_t)((b << 10) + r0 + warp)) << 10;
#pragma unroll
        for (int t2 = 0; t2 < 32; ++t2) {
            float vv = acc[t2] * 0.0625f;
            int j = t2 * 32 + lane;
            attn[base + j] = vv;
            if (attn_out) attn_out[base + j] = vv;
        }
    }
}

// ---------------- Launch ----------------------------------------------------
extern "C" void kernel_launch(void* const* d_in, const int* in_sizes, int n_in,
                              void* d_out, int out_size) {
    const float* q     = (const float*)d_in[0];
    const float* k     = (const float*)d_in[1];
    const float* v     = (const float*)d_in[2];
    const float* Wq    = (const float*)d_in[3];
    const float* Wk    = (const float*)d_in[4];
    const int*   kmask = (const int*)d_in[5];
    float*       out   = (float*)d_out;

    float *qp_ptr, *kp_ptr, *kT_ptr, *attn_ptr;
    cudaGetSymbolAddress((void**)&qp_ptr, g_qp);
    cudaGetSymbolAddress((void**)&kp_ptr, g_kp);
    cudaGetSymbolAddress((void**)&kT_ptr, g_kT);
    cudaGetSymbolAddress((void**)&attn_ptr, g_attn);

    float* attn_out = (out_size >= 2 * 4194304) ? (out + 4194304) : nullptr;

    // both projections in one launch (z=0: qp, z=1: kp)
    gemm_nt_kernel<<<dim3(8, 32, 2), 256>>>(q, Wq, qp_ptr, k, Wk, kp_ptr);

    // kp -> kT
    transpose_kernel<<<dim3(32, 32, 4), 256>>>(kp_ptr, kT_ptr);

    // fused scores + thresholded softmax + head mean
    attn_kernel<<<dim3(128, 4), 256>>>(qp_ptr, kT_ptr, kmask, attn_ptr, attn_out);

    // out = attn @ v
    gemm_nn_kernel<<<dim3(8, 8, 4), 256>>>(attn_ptr, v, out);
}

// round 6
// speedup vs baseline: 2.2534x; 1.7612x over previous
#include <cuda_runtime.h>
#include <cuda_bf16.h>
#include <math.h>
#include <float.h>
#include <stdint.h>

// B=4, Sq=Skv=1024, H=16, Dh=64. d_out: [out 4M][attn 4M] fp32.
// All tensor work via baseline-PTX mma.sync (HMMA) — tcgen05 is unavailable
// because the harness compiles through virtual arch compute_103 (no 'a').

__device__ __nv_bfloat16 g_inhi[8u << 20], g_inlo[8u << 20];  // q(scaled)|k
__device__ __nv_bfloat16 g_whi[2u << 20],  g_wlo[2u << 20];   // Wq|Wk
__device__ __nv_bfloat16 g_pphi[8u << 20], g_pplo[8u << 20];  // qp|kp (bf16 hi/lo)
__device__ float         g_scores[67108864];                   // [b*16+h][1024][1024]
__device__ __nv_bfloat16 g_athi[4u << 20], g_atlo[4u << 20];  // attn hi/lo
__device__ __nv_bfloat16 g_vthi[4u << 20], g_vtlo[4u << 20];  // v^T hi/lo

// ---------------- helpers ----------------------------------------------------
__device__ __forceinline__ uint32_t smem_u32(const void* p) {
    uint32_t a;
    asm("{ .reg .u64 t; cvta.to.shared.u64 t, %1; cvt.u32.u64 %0, t; }" : "=r"(a) : "l"(p));
    return a;
}
__device__ __forceinline__ void mma16816(float* c, const uint32_t* a, const uint32_t* b) {
    asm volatile(
        "mma.sync.aligned.m16n8k16.row.col.f32.bf16.bf16.f32 "
        "{%0,%1,%2,%3}, {%4,%5,%6,%7}, {%8,%9}, {%0,%1,%2,%3};"
        : "+f"(c[0]), "+f"(c[1]), "+f"(c[2]), "+f"(c[3])
        : "r"(a[0]), "r"(a[1]), "r"(a[2]), "r"(a[3]), "r"(b[0]), "r"(b[1]));
}
// A-frag (m16k16): sub0 rows r0..+7 @kb, sub1 rows +8 @kb, sub2 rows r0 @kb+1, sub3 rows +8 @kb+1
__device__ __forceinline__ void ldmA(uint32_t* r, uint32_t base, int row0, int kb, int lane) {
    int sub = lane >> 3, rr = lane & 7;
    int row = row0 + rr + ((sub & 1) << 3);
    int ch  = kb + (sub >> 1);
    uint32_t addr = base + row * 128 + ((ch ^ (row & 7)) << 4);
    asm volatile("ldmatrix.sync.aligned.m8n8.x4.shared.b16 {%0,%1,%2,%3}, [%4];"
                 : "=r"(r[0]), "=r"(r[1]), "=r"(r[2]), "=r"(r[3]) : "r"(addr));
}
// B-frags (2x n8k16): sub0 rows n0..+7 @kb, sub1 same rows @kb+1, sub2 rows +8 @kb, sub3 rows +8 @kb+1
__device__ __forceinline__ void ldmB(uint32_t* r, uint32_t base, int row0, int kb, int lane) {
    int sub = lane >> 3, rr = lane & 7;
    int row = row0 + rr + ((sub >> 1) << 3);
    int ch  = kb + (sub & 1);
    uint32_t addr = base + row * 128 + ((ch ^ (row & 7)) << 4);
    asm volatile("ldmatrix.sync.aligned.m8n8.x4.shared.b16 {%0,%1,%2,%3}, [%4];"
                 : "=r"(r[0]), "=r"(r[1]), "=r"(r[2]), "=r"(r[3]) : "r"(addr));
}

// ---------------- split fp32 -> bf16 hi/lo (optional scale) -----------------
__global__ void split_kernel(const float* __restrict__ in, __nv_bfloat16* __restrict__ hi,
                             __nv_bfloat16* __restrict__ lo, int n, float scale) {
    int i = (blockIdx.x * 256 + threadIdx.x) * 4;
    if (i >= n) return;
    float4 v = *(const float4*)(in + i);
    v.x *= scale; v.y *= scale; v.z *= scale; v.w *= scale;
    __nv_bfloat162 H0, H1, L0, L1;
    H0.x = __float2bfloat16(v.x); H0.y = __float2bfloat16(v.y);
    H1.x = __float2bfloat16(v.z); H1.y = __float2bfloat16(v.w);
    L0.x = __float2bfloat16(v.x - __bfloat162float(H0.x));
    L0.y = __float2bfloat16(v.y - __bfloat162float(H0.y));
    L1.x = __float2bfloat16(v.z - __bfloat162float(H1.x));
    L1.y = __float2bfloat16(v.w - __bfloat162float(H1.y));
    *(__nv_bfloat162*)(hi + i)     = H0;
    *(__nv_bfloat162*)(hi + i + 2) = H1;
    *(__nv_bfloat162*)(lo + i)     = L0;
    *(__nv_bfloat162*)(lo + i + 2) = L1;
}

// ---------------- v[b][k][n] -> vT hi/lo [b][n][k] ---------------------------
__global__ __launch_bounds__(256)
void transpose_split_v(const float* __restrict__ v, __nv_bfloat16* __restrict__ thi,
                       __nv_bfloat16* __restrict__ tlo) {
    __shared__ float tile[32][33];
    const int b = blockIdx.z, n0 = blockIdx.x * 32, k0 = blockIdx.y * 32;
    const int tx = threadIdx.x & 31, ty = threadIdx.x >> 5;
    const float* I = v + ((size_t)b << 20);
#pragma unroll
    for (int i = 0; i < 4; ++i)
        tile[ty + i * 8][tx] = I[(size_t)(k0 + ty + i * 8) * 1024 + n0 + tx];
    __syncthreads();
#pragma unroll
    for (int i = 0; i < 4; ++i) {
        float x = tile[tx][ty + i * 8];
        size_t o = ((size_t)b << 20) + (size_t)(n0 + ty + i * 8) * 1024 + k0 + tx;
        __nv_bfloat16 h = __float2bfloat16(x);
        thi[o] = h;
        tlo[o] = __float2bfloat16(x - __bfloat162float(h));
    }
}

// ---------------- split-bf16 NT GEMM via mma.sync ---------------------------
// C[z][m][n] = sum_k A[z][m][k]*B[z][n][k]; all row strides = 1024 elements.
// Per-z offsets: off = (z>>4)*MulHi + (z&15)*MulLo. 128x128 tile, 8 warps
// (2m x 4n), K staged in 64-chunks (Ahi|Alo|Bhi|Blo 16KB each, swizzled).
// BF16OUT: write bf16 hi/lo pair instead of fp32.
#define GEMM_SMEM 65536
template <int BF16OUT>
__global__ __launch_bounds__(256, 2)
void mma_gemm(const __nv_bfloat16* __restrict__ Ahi, const __nv_bfloat16* __restrict__ Alo,
              const __nv_bfloat16* __restrict__ Bhi, const __nv_bfloat16* __restrict__ Blo,
              float* __restrict__ Cf, __nv_bfloat16* __restrict__ Chi,
              __nv_bfloat16* __restrict__ Clo,
              size_t aMulHi, size_t aMulLo, size_t bMulHi, size_t bMulLo,
              size_t cMulHi, size_t cMulLo, int K) {
    extern __shared__ char smem[];
    const uint32_t sb = smem_u32(smem);
    const int tid = threadIdx.x, wid = tid >> 5, lane = tid & 31;
    const int m0 = blockIdx.y * 128, n0 = blockIdx.x * 128, z = blockIdx.z;
    const int wm = wid >> 2, wn = wid & 3;

    const size_t aoff = (size_t)(z >> 4) * aMulHi + (size_t)(z & 15) * aMulLo;
    const size_t boff = (size_t)(z >> 4) * bMulHi + (size_t)(z & 15) * bMulLo;
    const size_t coff = (size_t)(z >> 4) * cMulHi + (size_t)(z & 15) * cMulLo;

    const __nv_bfloat16* srcs[4] = {
        Ahi + aoff + (size_t)m0 * 1024, Alo + aoff + (size_t)m0 * 1024,
        Bhi + boff + (size_t)n0 * 1024, Blo + boff + (size_t)n0 * 1024 };

    float acc[4][4][4];
#pragma unroll
    for (int i = 0; i < 4; ++i)
#pragma unroll
        for (int j = 0; j < 4; ++j)
#pragma unroll
            for (int e = 0; e < 4; ++e) acc[i][j][e] = 0.f;

    const int lrow = tid >> 3, lc = tid & 7;
    const int nstage = K >> 6;
    for (int s = 0; s < nstage; ++s) {
        const int k0 = s << 6;
#pragma unroll
        for (int mat = 0; mat < 4; ++mat) {
            const __nv_bfloat16* sp = srcs[mat] + k0 + lc * 8;
            char* db = smem + mat * 16384;
#pragma unroll
            for (int i = 0; i < 4; ++i) {
                int row = lrow + i * 32;
                uint4 val = *(const uint4*)(sp + (size_t)row * 1024);
                *(uint4*)(db + row * 128 + ((lc ^ (row & 7)) << 4)) = val;
            }
        }
        __syncthreads();
#pragma unroll
        for (int ks = 0; ks < 4; ++ks) {
            const int kb = ks * 2;
            uint32_t ah[4][4], al[4][4];
#pragma unroll
            for (int fm = 0; fm < 4; ++fm) {
                ldmA(ah[fm], sb,         wm * 64 + fm * 16, kb, lane);
                ldmA(al[fm], sb + 16384, wm * 64 + fm * 16, kb, lane);
            }
#pragma unroll
            for (int nh = 0; nh < 2; ++nh) {
                uint32_t bh[4], bl[4];
                ldmB(bh, sb + 32768, wn * 32 + nh * 16, kb, lane);
                ldmB(bl, sb + 49152, wn * 32 + nh * 16, kb, lane);
#pragma unroll
                for (int fm = 0; fm < 4; ++fm) {
                    mma16816(acc[fm][2 * nh],     ah[fm], bh);
                    mma16816(acc[fm][2 * nh],     al[fm], bh);
                    mma16816(acc[fm][2 * nh],     ah[fm], bl);
                    mma16816(acc[fm][2 * nh + 1], ah[fm], bh + 2);
                    mma16816(acc[fm][2 * nh + 1], al[fm], bh + 2);
                    mma16816(acc[fm][2 * nh + 1], ah[fm], bl + 2);
                }
            }
        }
        __syncthreads();
    }

    const int g = lane >> 2, tig = lane & 3;
#pragma unroll
    for (int fm = 0; fm < 4; ++fm)
#pragma unroll
        for (int j = 0; j < 4; ++j) {
            int row = m0 + wm * 64 + fm * 16 + g;
            int col = n0 + wn * 32 + j * 8 + 2 * tig;
            float d0 = acc[fm][j][0], d1 = acc[fm][j][1];
            float d2 = acc[fm][j][2], d3 = acc[fm][j][3];
            if (BF16OUT) {
                __nv_bfloat162 h0, l0, h1, l1;
                h0.x = __float2bfloat16(d0); h0.y = __float2bfloat16(d1);
                l0.x = __float2bfloat16(d0 - __bfloat162float(h0.x));
                l0.y = __float2bfloat16(d1 - __bfloat162float(h0.y));
                h1.x = __float2bfloat16(d2); h1.y = __float2bfloat16(d3);
                l1.x = __float2bfloat16(d2 - __bfloat162float(h1.x));
                l1.y = __float2bfloat16(d3 - __bfloat162float(h1.y));
                *(__nv_bfloat162*)(Chi + coff + (size_t)row * 1024 + col)       = h0;
                *(__nv_bfloat162*)(Clo + coff + (size_t)row * 1024 + col)       = l0;
                *(__nv_bfloat162*)(Chi + coff + (size_t)(row + 8) * 1024 + col) = h1;
                *(__nv_bfloat162*)(Clo + coff + (size_t)(row + 8) * 1024 + col) = l1;
            } else {
                *(float2*)(Cf + coff + (size_t)row * 1024 + col)       = make_float2(d0, d1);
                *(float2*)(Cf + coff + (size_t)(row + 8) * 1024 + col) = make_float2(d2, d3);
            }
        }
}

// ---------------- select: softmax + cumulative-threshold + head mean --------
// CTA = (batch b, 8 q-rows), 256 thr; warp w owns row r0+w. Scores from gmem.
__global__ __launch_bounds__(256)
void select_kernel(const float* __restrict__ scores, const int* __restrict__ kmask,
                   float* __restrict__ attn_out,
                   __nv_bfloat16* __restrict__ ahi, __nv_bfloat16* __restrict__ alo) {
    __shared__ unsigned char km[1024];
    const int b = blockIdx.y, r0 = blockIdx.x * 8;
    const int tid = threadIdx.x, warp = tid >> 5, lane = tid & 31;

    for (int i = tid; i < 1024; i += 256)
        km[i] = (kmask[b * 1024 + i] > 0) ? 1 : 0;
    __syncthreads();

    float acc[32];
#pragma unroll
    for (int t2 = 0; t2 < 32; ++t2) acc[t2] = 0.f;

    const int row = r0 + warp;
    for (int h = 0; h < 16; ++h) {
        const float* rp = scores + (((size_t)(b * 16 + h)) << 20) + ((size_t)row << 10);
        float p[32];
        float m = -FLT_MAX;
#pragma unroll
        for (int c = 0; c < 8; ++c) {
            int j = c * 128 + lane * 4;
            float4 v = *(const float4*)(rp + j);
            p[c*4+0] = km[j+0] ? v.x : -FLT_MAX;
            p[c*4+1] = km[j+1] ? v.y : -FLT_MAX;
            p[c*4+2] = km[j+2] ? v.z : -FLT_MAX;
            p[c*4+3] = km[j+3] ? v.w : -FLT_MAX;
            m = fmaxf(m, fmaxf(fmaxf(p[c*4], p[c*4+1]), fmaxf(p[c*4+2], p[c*4+3])));
        }
#pragma unroll
        for (int o = 16; o > 0; o >>= 1)
            m = fmaxf(m, __shfl_xor_sync(0xffffffffu, m, o));

        float Z = 0.f;
#pragma unroll
        for (int t2 = 0; t2 < 32; ++t2) {
            float e = __expf(p[t2] - m);
            p[t2] = e;
            Z += e;
        }
#pragma unroll
        for (int o = 16; o > 0; o >>= 1)
            Z += __shfl_xor_sync(0xffffffffu, Z, o);

        const float T = 0.1f * Z;
        // exact weighted radix-select over positive-float bit patterns.
        // Base 0x38000000 provably below cutoff: G(2^-14) <= 1023*2^-14 < 0.1 <= T.
        unsigned P = 0x38000000u;
        for (int bit = 26; bit >= 0; --bit) {
            unsigned cand = P + (1u << bit);
            float S = 0.f;
#pragma unroll
            for (int t2 = 0; t2 < 32; ++t2)
                S += (__float_as_uint(p[t2]) < cand) ? p[t2] : 0.f;
#pragma unroll
            for (int o = 16; o > 0; o >>= 1)
                S += __shfl_xor_sync(0xffffffffu, S, o);
            if (S < T) P = cand;
        }

        float K = 0.f;
#pragma unroll
        for (int t2 = 0; t2 < 32; ++t2)
            K += (__float_as_uint(p[t2]) >= P) ? p[t2] : 0.f;
#pragma unroll
        for (int o = 16; o > 0; o >>= 1)
            K += __shfl_xor_sync(0xffffffffu, K, o);

        float inv = 1.f / (K + 1e-7f * Z);
#pragma unroll
        for (int t2 = 0; t2 < 32; ++t2)
            acc[t2] += (__float_as_uint(p[t2]) >= P) ? p[t2] * inv : 0.f;
    }

    {   // head-mean row -> d_out attn (fp32) + bf16 hi/lo for the out-GEMM
        size_t base = ((size_t)(b * 1024 + row)) << 10;
#pragma unroll
        for (int c = 0; c < 8; ++c) {
            int j = c * 128 + lane * 4;
            float4 v = make_float4(acc[c*4+0] * 0.0625f, acc[c*4+1] * 0.0625f,
                                   acc[c*4+2] * 0.0625f, acc[c*4+3] * 0.0625f);
            *(float4*)(attn_out + base + j) = v;
            __nv_bfloat162 h0, h1, l0, l1;
            h0.x = __float2bfloat16(v.x); h0.y = __float2bfloat16(v.y);
            h1.x = __float2bfloat16(v.z); h1.y = __float2bfloat16(v.w);
            l0.x = __float2bfloat16(v.x - __bfloat162float(h0.x));
            l0.y = __float2bfloat16(v.y - __bfloat162float(h0.y));
            l1.x = __float2bfloat16(v.z - __bfloat162float(h1.x));
            l1.y = __float2bfloat16(v.w - __bfloat162float(h1.y));
            *(__nv_bfloat162*)(ahi + base + j)     = h0;
            *(__nv_bfloat162*)(ahi + base + j + 2) = h1;
            *(__nv_bfloat162*)(alo + base + j)     = l0;
            *(__nv_bfloat162*)(alo + base + j + 2) = l1;
        }
    }
}

// ---------------- Launch ------------------------------------------------------
extern "C" void kernel_launch(void* const* d_in, const int* in_sizes, int n_in,
                              void* d_out, int out_size) {
    const float* q     = (const float*)d_in[0];
    const float* k     = (const float*)d_in[1];
    const float* v     = (const float*)d_in[2];
    const float* Wq    = (const float*)d_in[3];
    const float* Wk    = (const float*)d_in[4];
    const int*   kmask = (const int*)d_in[5];
    float*       out   = (float*)d_out;

    __nv_bfloat16 *inhi, *inlo, *whi, *wlo, *pphi, *pplo, *athi, *atlo, *vthi, *vtlo;
    float* scores;
    cudaGetSymbolAddress((void**)&inhi, g_inhi);
    cudaGetSymbolAddress((void**)&inlo, g_inlo);
    cudaGetSymbolAddress((void**)&whi,  g_whi);
    cudaGetSymbolAddress((void**)&wlo,  g_wlo);
    cudaGetSymbolAddress((void**)&pphi, g_pphi);
    cudaGetSymbolAddress((void**)&pplo, g_pplo);
    cudaGetSymbolAddress((void**)&scores, g_scores);
    cudaGetSymbolAddress((void**)&athi, g_athi);
    cudaGetSymbolAddress((void**)&atlo, g_atlo);
    cudaGetSymbolAddress((void**)&vthi, g_vthi);
    cudaGetSymbolAddress((void**)&vtlo, g_vtlo);

    cudaFuncSetAttribute(mma_gemm<0>, cudaFuncAttributeMaxDynamicSharedMemorySize, GEMM_SMEM);
    cudaFuncSetAttribute(mma_gemm<1>, cudaFuncAttributeMaxDynamicSharedMemorySize, GEMM_SMEM);

    const size_t M4 = 4u << 20, M1 = 1u << 20, M16 = 16u << 20;

    // split inputs; fold 1/sqrt(Dh)=0.125 into q
    split_kernel<<<4096, 256>>>(q,  inhi,      inlo,      (int)M4, 0.125f);
    split_kernel<<<4096, 256>>>(k,  inhi + M4, inlo + M4, (int)M4, 1.0f);
    split_kernel<<<1024, 256>>>(Wq, whi,       wlo,       (int)M1, 1.0f);
    split_kernel<<<1024, 256>>>(Wk, whi + M1,  wlo + M1,  (int)M1, 1.0f);

    // v -> vT hi/lo
    transpose_split_v<<<dim3(32, 32, 4), 256>>>(v, vthi, vtlo);

    // projections (z=0: qp, z=1: kp) -> bf16 hi/lo directly
    mma_gemm<1><<<dim3(8, 32, 2), 256, GEMM_SMEM>>>(
        inhi, inlo, whi, wlo, nullptr, pphi, pplo,
        0, M4, 0, M1, 0, M4, 1024);

    // scores[z=b*16+h] = qp_h @ kp_h^T (K=64); offsets b*1M + h*64
    mma_gemm<0><<<dim3(8, 8, 64), 256, GEMM_SMEM>>>(
        pphi, pplo, pphi + M4, pplo + M4, scores, nullptr, nullptr,
        M1, 64, M1, 64, M16, M1, 64);

    // softmax + cumulative-threshold select + head mean
    select_kernel<<<dim3(128, 4), 256>>>(scores, kmask, out + M4, athi, atlo);

    // out = attn @ vT^T (z=batch)
    mma_gemm<0><<<dim3(8, 8, 4), 256, GEMM_SMEM>>>(
        athi, atlo, vthi, vtlo, out, nullptr, nullptr,
        0, M1, 0, M1, 0, M1, 1024);
}

// round 7
// speedup vs baseline: 2.2844x; 1.0138x over previous
#include <cuda_runtime.h>
#include <cuda_bf16.h>
#include <math.h>
#include <float.h>
#include <stdint.h>

// B=4, Sq=Skv=1024, H=16, Dh=64. d_out: [out 4M][attn 4M] fp32.
// Tensor work via baseline-PTX mma.sync (HMMA): tcgen05 is unavailable because
// the harness compiles through virtual arch compute_103 (no 'a' suffix).

__device__ __nv_bfloat16 g_inhi[8u << 20], g_inlo[8u << 20];  // q(scaled)|k
__device__ __nv_bfloat16 g_whi[2u << 20],  g_wlo[2u << 20];   // Wq|Wk
__device__ __nv_bfloat16 g_pphi[8u << 20], g_pplo[8u << 20];  // qp|kp hi/lo
__device__ float         g_scores[67108864];                   // [b*16+h][1024][1024]
__device__ __nv_bfloat16 g_athi[4u << 20], g_atlo[4u << 20];  // attn hi/lo
__device__ __nv_bfloat16 g_vthi[4u << 20], g_vtlo[4u << 20];  // v^T hi/lo

// ---------------- helpers ----------------------------------------------------
__device__ __forceinline__ uint32_t smem_u32(const void* p) {
    uint32_t a;
    asm("{ .reg .u64 t; cvta.to.shared.u64 t, %1; cvt.u32.u64 %0, t; }" : "=r"(a) : "l"(p));
    return a;
}
__device__ __forceinline__ void mma16816(float* c, const uint32_t* a, const uint32_t* b) {
    asm volatile(
        "mma.sync.aligned.m16n8k16.row.col.f32.bf16.bf16.f32 "
        "{%0,%1,%2,%3}, {%4,%5,%6,%7}, {%8,%9}, {%0,%1,%2,%3};"
        : "+f"(c[0]), "+f"(c[1]), "+f"(c[2]), "+f"(c[3])
        : "r"(a[0]), "r"(a[1]), "r"(a[2]), "r"(a[3]), "r"(b[0]), "r"(b[1]));
}
__device__ __forceinline__ void ldmA(uint32_t* r, uint32_t base, int row0, int kb, int lane) {
    int sub = lane >> 3, rr = lane & 7;
    int row = row0 + rr + ((sub & 1) << 3);
    int ch  = kb + (sub >> 1);
    uint32_t addr = base + row * 128 + ((ch ^ (row & 7)) << 4);
    asm volatile("ldmatrix.sync.aligned.m8n8.x4.shared.b16 {%0,%1,%2,%3}, [%4];"
                 : "=r"(r[0]), "=r"(r[1]), "=r"(r[2]), "=r"(r[3]) : "r"(addr));
}
__device__ __forceinline__ void ldmB(uint32_t* r, uint32_t base, int row0, int kb, int lane) {
    int sub = lane >> 3, rr = lane & 7;
    int row = row0 + rr + ((sub >> 1) << 3);
    int ch  = kb + (sub & 1);
    uint32_t addr = base + row * 128 + ((ch ^ (row & 7)) << 4);
    asm volatile("ldmatrix.sync.aligned.m8n8.x4.shared.b16 {%0,%1,%2,%3}, [%4];"
                 : "=r"(r[0]), "=r"(r[1]), "=r"(r[2]), "=r"(r[3]) : "r"(addr));
}
#define CP_ASYNC16(dst, src) \
    asm volatile("cp.async.cg.shared.global [%0], [%1], 16;" :: "r"(dst), "l"(src))
#define CP_COMMIT() asm volatile("cp.async.commit_group;" ::: "memory")
#define CP_WAIT0()  asm volatile("cp.async.wait_group 0;" ::: "memory")

// ---------------- split fp32 -> bf16 hi/lo (optional scale) -----------------
__global__ void split_kernel(const float* __restrict__ in, __nv_bfloat16* __restrict__ hi,
                             __nv_bfloat16* __restrict__ lo, int n, float scale) {
    int i = (blockIdx.x * 256 + threadIdx.x) * 4;
    if (i >= n) return;
    float4 v = *(const float4*)(in + i);
    v.x *= scale; v.y *= scale; v.z *= scale; v.w *= scale;
    __nv_bfloat162 H0, H1, L0, L1;
    H0.x = __float2bfloat16(v.x); H0.y = __float2bfloat16(v.y);
    H1.x = __float2bfloat16(v.z); H1.y = __float2bfloat16(v.w);
    L0.x = __float2bfloat16(v.x - __bfloat162float(H0.x));
    L0.y = __float2bfloat16(v.y - __bfloat162float(H0.y));
    L1.x = __float2bfloat16(v.z - __bfloat162float(H1.x));
    L1.y = __float2bfloat16(v.w - __bfloat162float(H1.y));
    *(__nv_bfloat162*)(hi + i)     = H0;
    *(__nv_bfloat162*)(hi + i + 2) = H1;
    *(__nv_bfloat162*)(lo + i)     = L0;
    *(__nv_bfloat162*)(lo + i + 2) = L1;
}

// ---------------- v[b][k][n] -> vT hi/lo [b][n][k] ---------------------------
__global__ __launch_bounds__(256)
void transpose_split_v(const float* __restrict__ v, __nv_bfloat16* __restrict__ thi,
                       __nv_bfloat16* __restrict__ tlo) {
    __shared__ float tile[32][33];
    const int b = blockIdx.z, n0 = blockIdx.x * 32, k0 = blockIdx.y * 32;
    const int tx = threadIdx.x & 31, ty = threadIdx.x >> 5;
    const float* I = v + ((size_t)b << 20);
#pragma unroll
    for (int i = 0; i < 4; ++i)
        tile[ty + i * 8][tx] = I[(size_t)(k0 + ty + i * 8) * 1024 + n0 + tx];
    __syncthreads();
#pragma unroll
    for (int i = 0; i < 4; ++i) {
        float x = tile[tx][ty + i * 8];
        size_t o = ((size_t)b << 20) + (size_t)(n0 + ty + i * 8) * 1024 + k0 + tx;
        __nv_bfloat16 h = __float2bfloat16(x);
        thi[o] = h;
        tlo[o] = __float2bfloat16(x - __bfloat162float(h));
    }
}

// ---------------- split-bf16 NT GEMM via mma.sync, cp.async double-buffered -
// C[z][m][n] = sum_k A[z][m][k]*B[z][n][k]; row stride 1024 elements.
// Per-z offsets: off = (z>>4)*MulHi + (z&15)*MulLo. 128x128 tile, 8 warps
// (2m x 4n). K staged in 64-chunks; stage buffer = Ahi|Alo|Bhi|Blo 16KB each
// (SW-swizzled), double-buffered (2 x 64KB smem).
#define GEMM_SMEM 131072
template <int BF16OUT>
__global__ __launch_bounds__(256)
void mma_gemm(const __nv_bfloat16* __restrict__ Ahi, const __nv_bfloat16* __restrict__ Alo,
              const __nv_bfloat16* __restrict__ Bhi, const __nv_bfloat16* __restrict__ Blo,
              float* __restrict__ Cf, __nv_bfloat16* __restrict__ Chi,
              __nv_bfloat16* __restrict__ Clo,
              size_t aMulHi, size_t aMulLo, size_t bMulHi, size_t bMulLo,
              size_t cMulHi, size_t cMulLo, int K) {
    extern __shared__ char smem[];
    const uint32_t sb = smem_u32(smem);
    const int tid = threadIdx.x, wid = tid >> 5, lane = tid & 31;
    const int m0 = blockIdx.y * 128, n0 = blockIdx.x * 128, z = blockIdx.z;
    const int wm = wid >> 2, wn = wid & 3;

    const size_t aoff = (size_t)(z >> 4) * aMulHi + (size_t)(z & 15) * aMulLo;
    const size_t boff = (size_t)(z >> 4) * bMulHi + (size_t)(z & 15) * bMulLo;
    const size_t coff = (size_t)(z >> 4) * cMulHi + (size_t)(z & 15) * cMulLo;

    const __nv_bfloat16* srcs[4] = {
        Ahi + aoff + (size_t)m0 * 1024, Alo + aoff + (size_t)m0 * 1024,
        Bhi + boff + (size_t)n0 * 1024, Blo + boff + (size_t)n0 * 1024 };

    float acc[4][4][4];
#pragma unroll
    for (int i = 0; i < 4; ++i)
#pragma unroll
        for (int j = 0; j < 4; ++j)
#pragma unroll
            for (int e = 0; e < 4; ++e) acc[i][j][e] = 0.f;

    const int lrow = tid >> 3, lc = tid & 7;
    const int nstage = K >> 6;

    // prefetch stage 0 into buffer 0
    {
#pragma unroll
        for (int mat = 0; mat < 4; ++mat) {
            const __nv_bfloat16* sp = srcs[mat] + lc * 8;
#pragma unroll
            for (int i = 0; i < 4; ++i) {
                int row = lrow + i * 32;
                uint32_t dst = sb + mat * 16384 + row * 128 + ((lc ^ (row & 7)) << 4);
                CP_ASYNC16(dst, sp + (size_t)row * 1024);
            }
        }
        CP_COMMIT();
    }

    for (int s = 0; s < nstage; ++s) {
        CP_WAIT0();
        __syncthreads();   // stage s resident & all warps done with the buffer being refilled
        if (s + 1 < nstage) {
            const int k1 = (s + 1) << 6;
            const uint32_t bb = sb + ((s + 1) & 1) * 65536;
#pragma unroll
            for (int mat = 0; mat < 4; ++mat) {
                const __nv_bfloat16* sp = srcs[mat] + k1 + lc * 8;
#pragma unroll
                for (int i = 0; i < 4; ++i) {
                    int row = lrow + i * 32;
                    uint32_t dst = bb + mat * 16384 + row * 128 + ((lc ^ (row & 7)) << 4);
                    CP_ASYNC16(dst, sp + (size_t)row * 1024);
                }
            }
            CP_COMMIT();
        }
        const uint32_t cbuf = sb + (s & 1) * 65536;
#pragma unroll
        for (int ks = 0; ks < 4; ++ks) {
            const int kb = ks * 2;
            uint32_t ah[4][4], al[4][4];
#pragma unroll
            for (int fm = 0; fm < 4; ++fm) {
                ldmA(ah[fm], cbuf,         wm * 64 + fm * 16, kb, lane);
                ldmA(al[fm], cbuf + 16384, wm * 64 + fm * 16, kb, lane);
            }
#pragma unroll
            for (int nh = 0; nh < 2; ++nh) {
                uint32_t bh[4], bl[4];
                ldmB(bh, cbuf + 32768, wn * 32 + nh * 16, kb, lane);
                ldmB(bl, cbuf + 49152, wn * 32 + nh * 16, kb, lane);
#pragma unroll
                for (int fm = 0; fm < 4; ++fm) {
                    mma16816(acc[fm][2 * nh],     ah[fm], bh);
                    mma16816(acc[fm][2 * nh],     al[fm], bh);
                    mma16816(acc[fm][2 * nh],     ah[fm], bl);
                    mma16816(acc[fm][2 * nh + 1], ah[fm], bh + 2);
                    mma16816(acc[fm][2 * nh + 1], al[fm], bh + 2);
                    mma16816(acc[fm][2 * nh + 1], ah[fm], bl + 2);
                }
            }
        }
        __syncthreads();   // all warps done reading buffer s before it is refilled
    }

    const int g = lane >> 2, tig = lane & 3;
#pragma unroll
    for (int fm = 0; fm < 4; ++fm)
#pragma unroll
        for (int j = 0; j < 4; ++j) {
            int row = m0 + wm * 64 + fm * 16 + g;
            int col = n0 + wn * 32 + j * 8 + 2 * tig;
            float d0 = acc[fm][j][0], d1 = acc[fm][j][1];
            float d2 = acc[fm][j][2], d3 = acc[fm][j][3];
            if (BF16OUT) {
                __nv_bfloat162 h0, l0, h1, l1;
                h0.x = __float2bfloat16(d0); h0.y = __float2bfloat16(d1);
                l0.x = __float2bfloat16(d0 - __bfloat162float(h0.x));
                l0.y = __float2bfloat16(d1 - __bfloat162float(h0.y));
                h1.x = __float2bfloat16(d2); h1.y = __float2bfloat16(d3);
                l1.x = __float2bfloat16(d2 - __bfloat162float(h1.x));
                l1.y = __float2bfloat16(d3 - __bfloat162float(h1.y));
                *(__nv_bfloat162*)(Chi + coff + (size_t)row * 1024 + col)       = h0;
                *(__nv_bfloat162*)(Clo + coff + (size_t)row * 1024 + col)       = l0;
                *(__nv_bfloat162*)(Chi + coff + (size_t)(row + 8) * 1024 + col) = h1;
                *(__nv_bfloat162*)(Clo + coff + (size_t)(row + 8) * 1024 + col) = l1;
            } else {
                *(float2*)(Cf + coff + (size_t)row * 1024 + col)       = make_float2(d0, d1);
                *(float2*)(Cf + coff + (size_t)(row + 8) * 1024 + col) = make_float2(d2, d3);
            }
        }
}

// ---------------- select: softmax + cumulative-threshold + head mean --------
__global__ __launch_bounds__(256)
void select_kernel(const float* __restrict__ scores, const int* __restrict__ kmask,
                   float* __restrict__ attn_out,
                   __nv_bfloat16* __restrict__ ahi, __nv_bfloat16* __restrict__ alo) {
    __shared__ unsigned char km[1024];
    const int b = blockIdx.y, r0 = blockIdx.x * 8;
    const int tid = threadIdx.x, warp = tid >> 5, lane = tid & 31;

    for (int i = tid; i < 1024; i += 256)
        km[i] = (kmask[b * 1024 + i] > 0) ? 1 : 0;
    __syncthreads();

    float acc[32];
#pragma unroll
    for (int t2 = 0; t2 < 32; ++t2) acc[t2] = 0.f;

    const int row = r0 + warp;
    for (int h = 0; h < 16; ++h) {
        const float* rp = scores + (((size_t)(b * 16 + h)) << 20) + ((size_t)row << 10);
        float p[32];
        float m = -FLT_MAX;
#pragma unroll
        for (int c = 0; c < 8; ++c) {
            int j = c * 128 + lane * 4;
            float4 v = *(const float4*)(rp + j);
            p[c*4+0] = km[j+0] ? v.x : -FLT_MAX;
            p[c*4+1] = km[j+1] ? v.y : -FLT_MAX;
            p[c*4+2] = km[j+2] ? v.z : -FLT_MAX;
            p[c*4+3] = km[j+3] ? v.w : -FLT_MAX;
            m = fmaxf(m, fmaxf(fmaxf(p[c*4], p[c*4+1]), fmaxf(p[c*4+2], p[c*4+3])));
        }
#pragma unroll
        for (int o = 16; o > 0; o >>= 1)
            m = fmaxf(m, __shfl_xor_sync(0xffffffffu, m, o));

        float Z = 0.f;
#pragma unroll
        for (int t2 = 0; t2 < 32; ++t2) {
            float e = __expf(p[t2] - m);
            p[t2] = e;
            Z += e;
        }
#pragma unroll
        for (int o = 16; o > 0; o >>= 1)
            Z += __shfl_xor_sync(0xffffffffu, Z, o);

        const float T = 0.1f * Z;
        // exact weighted radix-select over positive-float bit patterns.
        // Base 0x38000000 provably below cutoff: G(2^-14) <= 1023*2^-14 < 0.1 <= T.
        unsigned P = 0x38000000u;
        for (int bit = 26; bit >= 0; --bit) {
            unsigned cand = P + (1u << bit);
            float S = 0.f;
#pragma unroll
            for (int t2 = 0; t2 < 32; ++t2)
                S += (__float_as_uint(p[t2]) < cand) ? p[t2] : 0.f;
#pragma unroll
            for (int o = 16; o > 0; o >>= 1)
                S += __shfl_xor_sync(0xffffffffu, S, o);
            if (S < T) P = cand;
        }

        float K = 0.f;
#pragma unroll
        for (int t2 = 0; t2 < 32; ++t2)
            K += (__float_as_uint(p[t2]) >= P) ? p[t2] : 0.f;
#pragma unroll
        for (int o = 16; o > 0; o >>= 1)
            K += __shfl_xor_sync(0xffffffffu, K, o);

        float inv = 1.f / (K + 1e-7f * Z);
#pragma unroll
        for (int t2 = 0; t2 < 32; ++t2)
            acc[t2] += (__float_as_uint(p[t2]) >= P) ? p[t2] * inv : 0.f;
    }

    {   // head-mean row -> d_out attn (fp32) + bf16 hi/lo for the out-GEMM
        size_t base = ((size_t)(b * 1024 + row)) << 10;
#pragma unroll
        for (int c = 0; c < 8; ++c) {
            int j = c * 128 + lane * 4;
            float4 v = make_float4(acc[c*4+0] * 0.0625f, acc[c*4+1] * 0.0625f,
                                   acc[c*4+2] * 0.0625f, acc[c*4+3] * 0.0625f);
            *(float4*)(attn_out + base + j) = v;
            __nv_bfloat162 h0, h1, l0, l1;
            h0.x = __float2bfloat16(v.x); h0.y = __float2bfloat16(v.y);
            h1.x = __float2bfloat16(v.z); h1.y = __float2bfloat16(v.w);
            l0.x = __float2bfloat16(v.x - __bfloat162float(h0.x));
            l0.y = __float2bfloat16(v.y - __bfloat162float(h0.y));
            l1.x = __float2bfloat16(v.z - __bfloat162float(h1.x));
            l1.y = __float2bfloat16(v.w - __bfloat162float(h1.y));
            *(__nv_bfloat162*)(ahi + base + j)     = h0;
            *(__nv_bfloat162*)(ahi + base + j + 2) = h1;
            *(__nv_bfloat162*)(alo + base + j)     = l0;
            *(__nv_bfloat162*)(alo + base + j + 2) = l1;
        }
    }
}

// ---------------- Launch ------------------------------------------------------
extern "C" void kernel_launch(void* const* d_in, const int* in_sizes, int n_in,
                              void* d_out, int out_size) {
    const float* q     = (const float*)d_in[0];
    const float* k     = (const float*)d_in[1];
    const float* v     = (const float*)d_in[2];
    const float* Wq    = (const float*)d_in[3];
    const float* Wk    = (const float*)d_in[4];
    const int*   kmask = (const int*)d_in[5];
    float*       out   = (float*)d_out;

    __nv_bfloat16 *inhi, *inlo, *whi, *wlo, *pphi, *pplo, *athi, *atlo, *vthi, *vtlo;
    float* scores;
    cudaGetSymbolAddress((void**)&inhi, g_inhi);
    cudaGetSymbolAddress((void**)&inlo, g_inlo);
    cudaGetSymbolAddress((void**)&whi,  g_whi);
    cudaGetSymbolAddress((void**)&wlo,  g_wlo);
    cudaGetSymbolAddress((void**)&pphi, g_pphi);
    cudaGetSymbolAddress((void**)&pplo, g_pplo);
    cudaGetSymbolAddress((void**)&scores, g_scores);
    cudaGetSymbolAddress((void**)&athi, g_athi);
    cudaGetSymbolAddress((void**)&atlo, g_atlo);
    cudaGetSymbolAddress((void**)&vthi, g_vthi);
    cudaGetSymbolAddress((void**)&vtlo, g_vtlo);

    cudaFuncSetAttribute(mma_gemm<0>, cudaFuncAttributeMaxDynamicSharedMemorySize, GEMM_SMEM);
    cudaFuncSetAttribute(mma_gemm<1>, cudaFuncAttributeMaxDynamicSharedMemorySize, GEMM_SMEM);

    const size_t M4 = 4u << 20, M1 = 1u << 20, M16 = 16u << 20;

    // split inputs; fold 1/sqrt(Dh)=0.125 into q
    split_kernel<<<4096, 256>>>(q,  inhi,      inlo,      (int)M4, 0.125f);
    split_kernel<<<4096, 256>>>(k,  inhi + M4, inlo + M4, (int)M4, 1.0f);
    split_kernel<<<1024, 256>>>(Wq, whi,       wlo,       (int)M1, 1.0f);
    split_kernel<<<1024, 256>>>(Wk, whi + M1,  wlo + M1,  (int)M1, 1.0f);

    // v -> vT hi/lo
    transpose_split_v<<<dim3(32, 32, 4), 256>>>(v, vthi, vtlo);

    // projections (z=0: qp, z=1: kp) -> bf16 hi/lo directly
    mma_gemm<1><<<dim3(8, 32, 2), 256, GEMM_SMEM>>>(
        inhi, inlo, whi, wlo, nullptr, pphi, pplo,
        0, M4, 0, M1, 0, M4, 1024);

    // scores[z=b*16+h] = qp_h @ kp_h^T (K=64); offsets b*1M + h*64
    mma_gemm<0><<<dim3(8, 8, 64), 256, GEMM_SMEM>>>(
        pphi, pplo, pphi + M4, pplo + M4, scores, nullptr, nullptr,
        M1, 64, M1, 64, M16, M1, 64);

    // softmax + cumulative-threshold select + head mean
    select_kernel<<<dim3(128, 4), 256>>>(scores, kmask, out + M4, athi, atlo);

    // out = attn @ vT^T (z=batch)
    mma_gemm<0><<<dim3(8, 8, 4), 256, GEMM_SMEM>>>(
        athi, atlo, vthi, vtlo, out, nullptr, nullptr,
        0, M1, 0, M1, 0, M1, 1024);
}